// round 1
// baseline (speedup 1.0000x reference)
#include <cuda_runtime.h>
#include <math.h>

// Problem constants
#define CDIM   512
#define NTOK   2048
#define BATCH  8
#define NLAYER 5
#define HALF   1024
#define MROWS  (BATCH*NTOK)   // 16384
#define QKVLD  (3*CDIM)       // 1536

// Scratch (device globals: allocation-free rule)
__device__ float g_qkv[(size_t)MROWS * QKVLD];          // 100 MB
__device__ float g_S  [(size_t)BATCH * NTOK * NTOK];    // 134 MB
__device__ float g_y  [(size_t)MROWS * CDIM];           //  32 MB
__device__ float g_h  [(size_t)MROWS * 2*CDIM];         //  64 MB

#define BM 128
#define BN 128
#define BK 16

// ---------------------------------------------------------------------------
// Generic SGEMM: C = A(MxK, ld=K) @ B(KxN, ld=N) + bias[N], epilogues:
//   EPI=0 none, EPI=1 exact GELU, EPI=2 residual add (C += ...)
// ---------------------------------------------------------------------------
template<int EPI>
__global__ __launch_bounds__(256)
void sgemm_bias(const float* __restrict__ A, const float* __restrict__ B,
                const float* __restrict__ bias, float* __restrict__ Cm,
                int M, int Nn, int K)
{
    __shared__ float As[BK][BM + 4];
    __shared__ float Bs[BK][BN];
    const int t  = threadIdx.x;
    const int tx = t & 15, ty = t >> 4;
    const int r0 = blockIdx.y * BM;
    const int c0 = blockIdx.x * BN;

    float acc[8][8];
#pragma unroll
    for (int i = 0; i < 8; i++)
#pragma unroll
        for (int j = 0; j < 8; j++) acc[i][j] = 0.f;

    for (int k0 = 0; k0 < K; k0 += BK) {
        // A tile: 128 rows x 16 k  (transposed store, padded)
#pragma unroll
        for (int i = 0; i < 2; i++) {
            int f = t + i * 256;
            int row = f >> 2, kq = f & 3;
            float4 v = *(const float4*)(A + (size_t)(r0 + row) * K + k0 + kq * 4);
            As[kq*4+0][row] = v.x; As[kq*4+1][row] = v.y;
            As[kq*4+2][row] = v.z; As[kq*4+3][row] = v.w;
        }
        // B tile: 16 k x 128 cols (direct, coalesced)
#pragma unroll
        for (int i = 0; i < 2; i++) {
            int f = t + i * 256;
            int kr = f >> 5, cq = f & 31;
            *(float4*)&Bs[kr][cq*4] =
                *(const float4*)(B + (size_t)(k0 + kr) * Nn + c0 + cq * 4);
        }
        __syncthreads();
#pragma unroll
        for (int k = 0; k < BK; k++) {
            float a[8], b[8];
            *(float4*)&a[0] = *(float4*)&As[k][ty*8];
            *(float4*)&a[4] = *(float4*)&As[k][ty*8+4];
            *(float4*)&b[0] = *(float4*)&Bs[k][tx*8];
            *(float4*)&b[4] = *(float4*)&Bs[k][tx*8+4];
#pragma unroll
            for (int i = 0; i < 8; i++)
#pragma unroll
                for (int j = 0; j < 8; j++) acc[i][j] += a[i] * b[j];
        }
        __syncthreads();
    }

#pragma unroll
    for (int i = 0; i < 8; i++) {
        int r = r0 + ty*8 + i;
#pragma unroll
        for (int j = 0; j < 8; j++) {
            int c = c0 + tx*8 + j;
            float v = acc[i][j] + bias[c];
            if (EPI == 1) v = 0.5f * v * (1.f + erff(v * 0.70710678118654752f));
            float* o = Cm + (size_t)r * Nn + c;
            if (EPI == 2) v += *o;
            *o = v;
        }
    }
}

// ---------------------------------------------------------------------------
// Scores: S[b] = scale * Q_b @ K_b^T  (skip fully-masked tiles)
// Q rows at QKV[b*NTOK*1536 + n*1536 + 0..511], K at +512
// ---------------------------------------------------------------------------
__global__ __launch_bounds__(256)
void scores_kernel(const float* __restrict__ QKV, float* __restrict__ S, float scale)
{
    const int bx = blockIdx.x, by = blockIdx.y, b = blockIdx.z;
    // mask tile skip: top half rows only attend j<HALF; bottom is causal
    if (by < (HALF/BM)) { if (bx >= (HALF/BM)) return; }
    else                { if (bx > by)          return; }

    __shared__ float As[BK][BM + 4];
    __shared__ float Bs[BK][BN + 4];
    const int t  = threadIdx.x;
    const int tx = t & 15, ty = t >> 4;
    const int r0 = by * BM, c0 = bx * BN;
    const float* Q  = QKV + (size_t)b * NTOK * QKVLD;
    const float* Kp = Q + CDIM;

    float acc[8][8];
#pragma unroll
    for (int i = 0; i < 8; i++)
#pragma unroll
        for (int j = 0; j < 8; j++) acc[i][j] = 0.f;

    for (int k0 = 0; k0 < CDIM; k0 += BK) {
#pragma unroll
        for (int i = 0; i < 2; i++) {
            int f = t + i * 256;
            int row = f >> 2, kq = f & 3;
            float4 v = *(const float4*)(Q + (size_t)(r0 + row) * QKVLD + k0 + kq * 4);
            As[kq*4+0][row] = v.x; As[kq*4+1][row] = v.y;
            As[kq*4+2][row] = v.z; As[kq*4+3][row] = v.w;
        }
#pragma unroll
        for (int i = 0; i < 2; i++) {
            int f = t + i * 256;
            int row = f >> 2, kq = f & 3;
            float4 v = *(const float4*)(Kp + (size_t)(c0 + row) * QKVLD + k0 + kq * 4);
            Bs[kq*4+0][row] = v.x; Bs[kq*4+1][row] = v.y;
            Bs[kq*4+2][row] = v.z; Bs[kq*4+3][row] = v.w;
        }
        __syncthreads();
#pragma unroll
        for (int k = 0; k < BK; k++) {
            float a[8], bb[8];
            *(float4*)&a[0]  = *(float4*)&As[k][ty*8];
            *(float4*)&a[4]  = *(float4*)&As[k][ty*8+4];
            *(float4*)&bb[0] = *(float4*)&Bs[k][tx*8];
            *(float4*)&bb[4] = *(float4*)&Bs[k][tx*8+4];
#pragma unroll
            for (int i = 0; i < 8; i++)
#pragma unroll
                for (int j = 0; j < 8; j++) acc[i][j] += a[i] * bb[j];
        }
        __syncthreads();
    }

    float* Sp = S + (size_t)b * NTOK * NTOK;
#pragma unroll
    for (int i = 0; i < 8; i++) {
        int r = r0 + ty*8 + i;
#pragma unroll
        for (int j = 0; j < 8; j++)
            Sp[(size_t)r * NTOK + c0 + tx*8 + j] = acc[i][j] * scale;
    }
}

// ---------------------------------------------------------------------------
// Masked softmax over each row of S (exact: masked entries underflow to 0 in
// the reference since bias = -1000; we skip them and zero-fill).
// ---------------------------------------------------------------------------
__global__ __launch_bounds__(256)
void softmax_kernel(float* __restrict__ S)
{
    const int row = blockIdx.x;             // 0..16383
    const int b = row >> 11, i = row & (NTOK - 1);
    const int limit = (i < HALF) ? HALF : (i + 1);
    float* p = S + (size_t)b * NTOK * NTOK + (size_t)i * NTOK;
    const int t = threadIdx.x;

    float vals[8];
    float m = -1e30f;
#pragma unroll
    for (int j = 0; j < 8; j++) {
        int idx = t + j * 256;
        vals[j] = (idx < limit) ? p[idx] : -1e30f;
        m = fmaxf(m, vals[j]);
    }
    __shared__ float red[256];
    red[t] = m; __syncthreads();
    for (int s = 128; s > 0; s >>= 1) {
        if (t < s) red[t] = fmaxf(red[t], red[t + s]);
        __syncthreads();
    }
    m = red[0]; __syncthreads();

    float sum = 0.f;
#pragma unroll
    for (int j = 0; j < 8; j++) {
        int idx = t + j * 256;
        if (idx < limit) { vals[j] = expf(vals[j] - m); sum += vals[j]; }
        else vals[j] = 0.f;
    }
    red[t] = sum; __syncthreads();
    for (int s = 128; s > 0; s >>= 1) {
        if (t < s) red[t] += red[t + s];
        __syncthreads();
    }
    const float inv = 1.f / red[0];
#pragma unroll
    for (int j = 0; j < 8; j++)
        p[t + j * 256] = vals[j] * inv;     // masked positions get exact 0
}

// ---------------------------------------------------------------------------
// out = S @ V, with reduction truncated per row-block (S is 0 beyond limit)
// V rows at QKV[... + 1024], ld=1536
// ---------------------------------------------------------------------------
__global__ __launch_bounds__(256)
void attnv_kernel(const float* __restrict__ S, const float* __restrict__ QKV,
                  float* __restrict__ out)
{
    const int bx = blockIdx.x, by = blockIdx.y, b = blockIdx.z;
    const int r0 = by * BM, c0 = bx * BN;
    const int kmax = (by < HALF/BM) ? HALF : (r0 + BM);

    __shared__ float As[BK][BM + 4];
    __shared__ float Bs[BK][BN];
    const int t  = threadIdx.x;
    const int tx = t & 15, ty = t >> 4;
    const float* Sp = S + (size_t)b * NTOK * NTOK;
    const float* V  = QKV + (size_t)b * NTOK * QKVLD + 2*CDIM;

    float acc[8][8];
#pragma unroll
    for (int i = 0; i < 8; i++)
#pragma unroll
        for (int j = 0; j < 8; j++) acc[i][j] = 0.f;

    for (int k0 = 0; k0 < kmax; k0 += BK) {
#pragma unroll
        for (int i = 0; i < 2; i++) {
            int f = t + i * 256;
            int row = f >> 2, kq = f & 3;
            float4 v = *(const float4*)(Sp + (size_t)(r0 + row) * NTOK + k0 + kq * 4);
            As[kq*4+0][row] = v.x; As[kq*4+1][row] = v.y;
            As[kq*4+2][row] = v.z; As[kq*4+3][row] = v.w;
        }
#pragma unroll
        for (int i = 0; i < 2; i++) {
            int f = t + i * 256;
            int kr = f >> 5, cq = f & 31;
            *(float4*)&Bs[kr][cq*4] =
                *(const float4*)(V + (size_t)(k0 + kr) * QKVLD + c0 + cq * 4);
        }
        __syncthreads();
#pragma unroll
        for (int k = 0; k < BK; k++) {
            float a[8], bb[8];
            *(float4*)&a[0]  = *(float4*)&As[k][ty*8];
            *(float4*)&a[4]  = *(float4*)&As[k][ty*8+4];
            *(float4*)&bb[0] = *(float4*)&Bs[k][tx*8];
            *(float4*)&bb[4] = *(float4*)&Bs[k][tx*8+4];
#pragma unroll
            for (int i = 0; i < 8; i++)
#pragma unroll
                for (int j = 0; j < 8; j++) acc[i][j] += a[i] * bb[j];
        }
        __syncthreads();
    }

#pragma unroll
    for (int i = 0; i < 8; i++) {
        int r = r0 + ty*8 + i;
#pragma unroll
        for (int j = 0; j < 8; j++)
            out[(size_t)(b * NTOK + r) * CDIM + c0 + tx*8 + j] = acc[i][j];
    }
}

// ---------------------------------------------------------------------------
// LayerNorm (two-pass, matches reference formula, eps=1e-5)
// ---------------------------------------------------------------------------
__global__ __launch_bounds__(256)
void layernorm_kernel(const float* __restrict__ X, const float* __restrict__ g,
                      const float* __restrict__ bta, float* __restrict__ Y)
{
    const int row = blockIdx.x;
    const float* x = X + (size_t)row * CDIM;
    const int t = threadIdx.x;
    float v0 = x[t], v1 = x[t + 256];

    __shared__ float red[256];
    red[t] = v0 + v1; __syncthreads();
    for (int s = 128; s > 0; s >>= 1) {
        if (t < s) red[t] += red[t + s];
        __syncthreads();
    }
    const float mu = red[0] * (1.f / CDIM);
    __syncthreads();

    float d0 = v0 - mu, d1 = v1 - mu;
    red[t] = d0*d0 + d1*d1; __syncthreads();
    for (int s = 128; s > 0; s >>= 1) {
        if (t < s) red[t] += red[t + s];
        __syncthreads();
    }
    const float inv = rsqrtf(red[0] * (1.f / CDIM) + 1e-5f);
    Y[(size_t)row * CDIM + t]       = d0 * inv * g[t]       + bta[t];
    Y[(size_t)row * CDIM + t + 256] = d1 * inv * g[t + 256] + bta[t + 256];
}

// ---------------------------------------------------------------------------
extern "C" void kernel_launch(void* const* d_in, const int* in_sizes, int n_in,
                              void* d_out, int out_size)
{
    const float* x_in  = (const float*)d_in[0];
    const float* qkv_w = (const float*)d_in[1];
    const float* qkv_b = (const float*)d_in[2];
    const float* ln_g  = (const float*)d_in[3];
    const float* ln_b  = (const float*)d_in[4];
    const float* fc1_w = (const float*)d_in[5];
    const float* fc1_b = (const float*)d_in[6];
    const float* fc2_w = (const float*)d_in[7];
    const float* fc2_b = (const float*)d_in[8];
    float* out = (float*)d_out;

    float *qkv, *S, *y, *h;
    cudaGetSymbolAddress((void**)&qkv, g_qkv);
    cudaGetSymbolAddress((void**)&S,   g_S);
    cudaGetSymbolAddress((void**)&y,   g_y);
    cudaGetSymbolAddress((void**)&h,   g_h);

    const float scale = 0.044194173824159216f;   // 512^-0.5
    const dim3 thr(256);

    for (int l = 0; l < NLAYER; l++) {
        const float* src = (l == 0) ? x_in : out;

        // 1. qkv = src @ qkv_w[l] + qkv_b[l]       (16384 x 1536, K=512)
        sgemm_bias<0><<<dim3(QKVLD/BN, MROWS/BM), thr>>>(
            src, qkv_w + (size_t)l*CDIM*QKVLD, qkv_b + (size_t)l*QKVLD,
            qkv, MROWS, QKVLD, CDIM);

        // 2. S = scale * Q K^T (masked tiles skipped)
        scores_kernel<<<dim3(NTOK/BN, NTOK/BM, BATCH), thr>>>(qkv, S, scale);

        // 3. masked softmax rows
        softmax_kernel<<<MROWS, thr>>>(S);

        // 4. x = S @ V  -> out
        attnv_kernel<<<dim3(CDIM/BN, NTOK/BM, BATCH), thr>>>(S, qkv, out);

        // 5. y = LN(x)
        layernorm_kernel<<<MROWS, thr>>>(out, ln_g + (size_t)l*CDIM,
                                         ln_b + (size_t)l*CDIM, y);

        // 6. h = gelu(y @ fc1_w[l] + fc1_b[l])     (16384 x 1024, K=512)
        sgemm_bias<1><<<dim3(2*CDIM/BN, MROWS/BM), thr>>>(
            y, fc1_w + (size_t)l*CDIM*2*CDIM, fc1_b + (size_t)l*2*CDIM,
            h, MROWS, 2*CDIM, CDIM);

        // 7. x += h @ fc2_w[l] + fc2_b[l]          (16384 x 512, K=1024)
        sgemm_bias<2><<<dim3(CDIM/BN, MROWS/BM), thr>>>(
            h, fc2_w + (size_t)l*2*CDIM*CDIM, fc2_b + (size_t)l*CDIM,
            out, MROWS, CDIM, 2*CDIM);
    }
}